// round 15
// baseline (speedup 1.0000x reference)
#include <cuda_runtime.h>
#include <cuda_fp16.h>
#include <cstdint>

// Problem constants
#define B_    32
#define C_    256
#define HW_   1024
#define N_    32768          // B_*HW_
#define K_    1024
#define QSIZE 8388608        // B_*C_*HW_
#define CAPS  16             // candidates per (row, n-slice)
#define DELTA 2.5e-3f

__device__ float g_enorm[K_];
__device__ float g_apart[4 * N_];           // per-64c-block partial |z|^2
__device__ float g_loss;
__device__ int   g_cnt[N_ * 4];             // per (row, slice) candidate count
__device__ int   g_cand[(size_t)N_ * 4 * CAPS];
__device__ __half g_Ah[(size_t)N_ * C_];    // x rows hi plane, [n][256]
__device__ __half g_Am[(size_t)N_ * C_];    // x rows residual plane
__device__ __half g_Bh[(size_t)K_ * C_];    // codebook hi plane, [k][256]

// ---------------------------------------------------------------------------
// PTX helpers
// ---------------------------------------------------------------------------
__device__ __forceinline__ uint32_t smem_u32(const void* p) {
    uint32_t a;
    asm("{ .reg .u64 t; cvta.to.shared.u64 t, %1; cvt.u32.u64 %0, t; }" : "=r"(a) : "l"(p));
    return a;
}
__device__ __forceinline__ void cp16(uint32_t daddr, const void* g) {
    asm volatile("cp.async.cg.shared.global [%0], [%1], 16;" :: "r"(daddr), "l"(g));
}
#define CP_COMMIT()  asm volatile("cp.async.commit_group;")
#define CP_WAIT0()   asm volatile("cp.async.wait_group 0;")

__device__ __forceinline__ void ldsm4(uint32_t* r, uint32_t addr) {
    asm volatile("ldmatrix.sync.aligned.m8n8.x4.shared.b16 {%0,%1,%2,%3}, [%4];"
        : "=r"(r[0]), "=r"(r[1]), "=r"(r[2]), "=r"(r[3]) : "r"(addr));
}
__device__ __forceinline__ void mma16816(float* d, const uint32_t* a, const uint32_t* b) {
    asm volatile(
        "mma.sync.aligned.m16n8k16.row.col.f32.f16.f16.f32 "
        "{%0,%1,%2,%3},{%4,%5,%6,%7},{%8,%9},{%0,%1,%2,%3};"
        : "+f"(d[0]), "+f"(d[1]), "+f"(d[2]), "+f"(d[3])
        : "r"(a[0]), "r"(a[1]), "r"(a[2]), "r"(a[3]), "r"(b[0]), "r"(b[1]));
}

// ---------------------------------------------------------------------------
// Launch #1: codebook -> fp16 plane; blocks 0-3 also enorm; thread 0 zeroes loss.
// ---------------------------------------------------------------------------
__global__ void prep_cb_kernel(const float* __restrict__ cb) {
    int i = blockIdx.x * blockDim.x + threadIdx.x;   // 0 .. 262143
    if (i == 0) g_loss = 0.0f;
    g_Bh[i] = __float2half_rn(cb[i]);
    if (blockIdx.x < 4) {
        int k = blockIdx.x * blockDim.x + threadIdx.x;
        const float4* row = reinterpret_cast<const float4*>(cb + (size_t)k * C_);
        float s = 0.f;
        #pragma unroll
        for (int q = 0; q < C_ / 4; ++q) {
            float4 v = row[q];
            s += v.x * v.x + v.y * v.y + v.z * v.z + v.w * v.w;
        }
        g_enorm[k] = s;
    }
}

// ---------------------------------------------------------------------------
// Launch #2: transpose x -> 2 fp16 planes + |z|^2 partials (one sync).
// ---------------------------------------------------------------------------
__global__ void prep_x_kernel(const float* __restrict__ x) {
    __shared__ float tile[64][65];
    __shared__ float sp[16][8];
    int bid = blockIdx.x;          // 2048 blocks
    int b   = bid >> 6;
    int rem = bid & 63;
    int cb4 = rem >> 4;
    int c0  = cb4 << 6;
    int hw0 = (rem & 15) << 6;
    int tid = threadIdx.x;
    int lane = tid & 31, wid = tid >> 5;

    #pragma unroll
    for (int i = 0; i < 16; ++i) {
        int cc = i * 4 + (tid >> 6);
        int hw = tid & 63;
        tile[cc][hw] = x[((size_t)b * C_ + c0 + cc) * HW_ + hw0 + hw];
    }
    __syncthreads();
    #pragma unroll
    for (int i = 0; i < 16; ++i) {
        int hh = i * 4 + (tid >> 6);
        int ci = tid & 63;
        float v = tile[ci][hh];
        __half h = __float2half_rn(v);
        __half m = __float2half_rn(v - __half2float(h));
        size_t o = (size_t)(b * HW_ + hw0 + hh) * C_ + c0 + ci;
        g_Ah[o] = h; g_Am[o] = m;

        float s = v * v;
        #pragma unroll
        for (int off = 16; off; off >>= 1) s += __shfl_xor_sync(0xffffffffu, s, off);
        if (lane == 0) sp[i][wid] = s;
    }
    __syncthreads();
    if (tid < 64) {
        int i = tid >> 2, pr = tid & 3;
        g_apart[cb4 * N_ + b * HW_ + hw0 + i * 4 + pr] = sp[i][2 * pr] + sp[i][2 * pr + 1];
    }
}

// ---------------------------------------------------------------------------
// Launch #3: GEMM (R14 measured-best, unchanged). grid (256,4), 512 threads.
// ---------------------------------------------------------------------------
#define APITCH 72
#define ABUF_B (128 * APITCH * 2)
#define BBUF_B (256 * APITCH * 2)
#define SDIST_OFF (2 * ABUF_B + 2 * BBUF_B)
#define DPITCH 258
#define SM_GEMM (SDIST_OFF + 128 * DPITCH * 2)
#define NKC 4

__global__ __launch_bounds__(512, 1)
void vq_gemm_kernel()
{
    extern __shared__ __align__(16) char dsm[];
    const uint32_t smA = smem_u32(dsm);
    const uint32_t smB = smA + 2 * ABUF_B;

    __shared__ float sEn[256];

    const int tid  = threadIdx.x;
    const int lane = tid & 31;
    const int wid  = tid >> 5;
    const int wm   = wid >> 3;
    const int wn   = wid & 7;

    const int m0 = blockIdx.x << 7;
    const int n0 = blockIdx.y << 8;

    if (tid < 256) sEn[tid] = g_enorm[n0 + tid];

    const __half* Ag = g_Ah + (size_t)m0 * C_;
    const __half* Bg = g_Bh + (size_t)n0 * C_;

    float acc[4][4][4];
    #pragma unroll
    for (int mf = 0; mf < 4; ++mf)
        #pragma unroll
        for (int nf = 0; nf < 4; ++nf)
            #pragma unroll
            for (int q = 0; q < 4; ++q) acc[mf][nf][q] = 0.f;

    const uint32_t aAddr0 = smA + (uint32_t)(((wm * 64 + (lane & 15)) * APITCH + ((lane >> 4) << 3)) * 2);
    const uint32_t bAddr0 = smB + (uint32_t)(((wn * 32 + (lane & 7) + ((lane >> 4) << 3)) * APITCH
                                              + (((lane >> 3) & 1) << 3)) * 2);

    {
        #pragma unroll
        for (int j = 0; j < 2; ++j) {
            int p = tid + j * 512, row = p >> 3, kp = (p & 7) << 3;
            cp16(smA + (uint32_t)((row * APITCH + kp) * 2), Ag + (size_t)row * C_ + kp);
        }
        #pragma unroll
        for (int j = 0; j < 4; ++j) {
            int p = tid + j * 512, row = p >> 3, kp = (p & 7) << 3;
            cp16(smB + (uint32_t)((row * APITCH + kp) * 2), Bg + (size_t)row * C_ + kp);
        }
        CP_COMMIT();
    }

    for (int it = 0; it < NKC; ++it) {
        CP_WAIT0();
        __syncthreads();

        if (it + 1 < NKC) {
            const int nb = (it + 1) & 1;
            const int k0 = (it + 1) << 6;
            #pragma unroll
            for (int j = 0; j < 2; ++j) {
                int p = tid + j * 512, row = p >> 3, kp = (p & 7) << 3;
                cp16(smA + (uint32_t)(nb * ABUF_B + (row * APITCH + kp) * 2),
                     Ag + (size_t)row * C_ + k0 + kp);
            }
            #pragma unroll
            for (int j = 0; j < 4; ++j) {
                int p = tid + j * 512, row = p >> 3, kp = (p & 7) << 3;
                cp16(smB + (uint32_t)(nb * BBUF_B + (row * APITCH + kp) * 2),
                     Bg + (size_t)row * C_ + k0 + kp);
            }
            CP_COMMIT();
        }

        const int buf = it & 1;
        const uint32_t aB = aAddr0 + (uint32_t)(buf * ABUF_B);
        const uint32_t bB = bAddr0 + (uint32_t)(buf * BBUF_B);

        #pragma unroll
        for (int ks = 0; ks < 4; ++ks) {
            uint32_t a[4][4], bfr[2][4];
            #pragma unroll
            for (int mf = 0; mf < 4; ++mf)
                ldsm4(a[mf], aB + (uint32_t)(mf * 16 * APITCH * 2 + ks * 32));
            #pragma unroll
            for (int nb2 = 0; nb2 < 2; ++nb2)
                ldsm4(bfr[nb2], bB + (uint32_t)(nb2 * 16 * APITCH * 2 + ks * 32));
            #pragma unroll
            for (int mf = 0; mf < 4; ++mf)
                #pragma unroll
                for (int nf = 0; nf < 4; ++nf)
                    mma16816(acc[mf][nf], a[mf], &bfr[nf >> 1][(nf & 1) << 1]);
        }
    }

    const int rb  = (wm << 6) + (lane >> 2);
    const int cl0 = (wn << 5) + ((lane & 3) << 1);
    #pragma unroll
    for (int mf = 0; mf < 4; ++mf) {
        #pragma unroll
        for (int hv = 0; hv < 2; ++hv) {
            int lrow = rb + mf * 16 + hv * 8;
            #pragma unroll
            for (int nf = 0; nf < 4; ++nf) {
                int cl = cl0 + nf * 8;
                float t0 = fmaf(-2.0f, acc[mf][nf][hv * 2 + 0], sEn[cl]);
                float t1 = fmaf(-2.0f, acc[mf][nf][hv * 2 + 1], sEn[cl + 1]);
                *reinterpret_cast<__half2*>(dsm + SDIST_OFF + ((size_t)lrow * DPITCH + cl) * 2)
                    = __floats2half2_rn(t0, t1);
            }
        }
    }
    __syncthreads();

    if (tid < 128) {
        const __half2* rowp =
            reinterpret_cast<const __half2*>(dsm + SDIST_OFF + (size_t)tid * DPITCH * 2);
        float mn = 3.4e38f;
        #pragma unroll 8
        for (int i = 0; i < 128; ++i) {
            __half2 h2 = rowp[i];
            float f0 = __low2float(h2), f1 = __high2float(h2);
            if (f0 < mn) mn = f0;
            if (f1 < mn) mn = f1;
        }
        float thr = mn + DELTA;
        int slot = ((m0 + tid) << 2) + blockIdx.y;
        int* cl = g_cand + (size_t)slot * CAPS;
        int cnt = 0;
        #pragma unroll 8
        for (int i = 0; i < 128; ++i) {
            __half2 h2 = rowp[i];
            float f0 = __low2float(h2), f1 = __high2float(h2);
            if (f0 <= thr && cnt < CAPS) cl[cnt++] = n0 + 2 * i;
            if (f1 <= thr && cnt < CAPS) cl[cnt++] = n0 + 2 * i + 1;
        }
        g_cnt[slot] = cnt;
    }
}

// ---------------------------------------------------------------------------
// Launch #4 (PROFILED): fused recheck + gather + loss.
// Phase 1: each warp rechecks its 16 rows (warp-collective exact fp32 dots,
//          R13-proven). Phase 2: stage the 128 selected codebook rows into
//          smem (coalesced), then straight-through output + MSE.
// ---------------------------------------------------------------------------
#define GP 257
#define SM_GR (128 * GP * 4)   // 131584 dynamic smem

__global__ __launch_bounds__(256)
void gr_kernel(const float* __restrict__ x,
               const float* __restrict__ cb,
               float* __restrict__ out)
{
    extern __shared__ __align__(16) float sq[];   // [128][GP]
    __shared__ int   cands[8][4 * CAPS];
    __shared__ int   srow[128];
    __shared__ float wsum[8];

    const int tid = threadIdx.x;
    const int lane = tid & 31;
    const int w    = tid >> 5;
    const int blk = blockIdx.x;
    const int b   = blk >> 3;
    const int hw0 = (blk & 7) << 7;
    const int m0  = blk << 7;

    // ---- phase 1: recheck 16 rows per warp ---------------------------------
    for (int r = 0; r < 16; ++r) {
        const int lm  = w * 16 + r;
        const int row = m0 + lm;

        float xr[8];
        {
            const __half* ah = g_Ah + (size_t)row * C_;
            const __half* am = g_Am + (size_t)row * C_;
            uint4 hvv = *reinterpret_cast<const uint4*>(ah + lane * 8);
            uint4 mvv = *reinterpret_cast<const uint4*>(am + lane * 8);
            const __half* hp = reinterpret_cast<const __half*>(&hvv);
            const __half* mp = reinterpret_cast<const __half*>(&mvv);
            #pragma unroll
            for (int j = 0; j < 8; ++j)
                xr[j] = __half2float(hp[j]) + __half2float(mp[j]);
        }

        int nct = 0;
        #pragma unroll
        for (int y = 0; y < 4; ++y) {
            int slot = row * 4 + y;
            int cy = g_cnt[slot];
            if (lane < cy) cands[w][nct + lane] = g_cand[(size_t)slot * CAPS + lane];
            nct += cy;
        }
        __syncwarp();

        float a = ((g_apart[row] + g_apart[N_ + row]) + g_apart[2 * N_ + row]) + g_apart[3 * N_ + row];
        unsigned long long eb = 0xFFFFFFFFFFFFFFFFull;
        for (int j = 0; j < nct; ++j) {
            int k = cands[w][j];
            const float4* cr = reinterpret_cast<const float4*>(cb + (size_t)k * C_) + lane * 2;
            float4 c0 = cr[0], c1 = cr[1];
            float p = 0.f;
            p = fmaf(xr[0], c0.x, p); p = fmaf(xr[1], c0.y, p);
            p = fmaf(xr[2], c0.z, p); p = fmaf(xr[3], c0.w, p);
            p = fmaf(xr[4], c1.x, p); p = fmaf(xr[5], c1.y, p);
            p = fmaf(xr[6], c1.z, p); p = fmaf(xr[7], c1.w, p);
            #pragma unroll
            for (int off = 16; off; off >>= 1)
                p += __shfl_xor_sync(0xffffffffu, p, off);
            float s = (a + g_enorm[k]) - 2.0f * p;
            unsigned long long pk =
                ((unsigned long long)__float_as_uint(s) << 32) | (unsigned)k;
            if (pk < eb) eb = pk;
        }
        if (lane == 0) {
            int idx = (int)(unsigned)(eb & 0xFFFFFFFFull);
            srow[lm] = idx;
            out[QSIZE + 1 + row] = (float)idx;
        }
        __syncwarp();
    }
    __syncthreads();

    // ---- phase 2: stage selected codebook rows (coalesced), then gather ----
    #pragma unroll
    for (int r = 0; r < 16; ++r) {
        int m = w * 16 + r;
        const float* cr = cb + (size_t)srow[m] * C_;
        #pragma unroll
        for (int j = 0; j < 8; ++j)
            sq[m * GP + lane + 32 * j] = __ldg(cr + lane + 32 * j);
    }
    __syncthreads();

    const float* xblk = x   + (size_t)b * (C_ * HW_) + hw0;
    float*       qblk = out + (size_t)b * (C_ * HW_) + hw0;
    float lsum = 0.f;
    #pragma unroll 4
    for (int it = 0; it < 32; ++it) {
        int l  = it * 256 + tid;
        int m4 = (l & 31) << 2;
        int c  = l >> 5;
        float4 xv = *reinterpret_cast<const float4*>(xblk + c * HW_ + m4);
        float q0 = sq[(m4 + 0) * GP + c];
        float q1 = sq[(m4 + 1) * GP + c];
        float q2 = sq[(m4 + 2) * GP + c];
        float q3 = sq[(m4 + 3) * GP + c];
        float d0 = q0 - xv.x, d1 = q1 - xv.y, d2 = q2 - xv.z, d3 = q3 - xv.w;
        float4 o;
        o.x = xv.x + d0; o.y = xv.y + d1; o.z = xv.z + d2; o.w = xv.w + d3;
        *reinterpret_cast<float4*>(qblk + c * HW_ + m4) = o;
        lsum += d0 * d0 + d1 * d1 + d2 * d2 + d3 * d3;
    }

    #pragma unroll
    for (int off = 16; off; off >>= 1)
        lsum += __shfl_xor_sync(0xffffffffu, lsum, off);
    if (lane == 0) wsum[w] = lsum;
    __syncthreads();
    if (tid == 0) {
        float s = 0.f;
        #pragma unroll
        for (int w2 = 0; w2 < 8; ++w2) s += wsum[w2];
        atomicAdd(&g_loss, s);
    }
}

__global__ void finalize_kernel(float* __restrict__ out) {
    out[QSIZE] = 1.25f * g_loss * (1.0f / (float)QSIZE);
}

extern "C" void kernel_launch(void* const* d_in, const int* in_sizes, int n_in,
                              void* d_out, int out_size) {
    (void)in_sizes; (void)n_in; (void)out_size;
    const float* x  = (const float*)d_in[0];
    const float* cb = (const float*)d_in[1];
    float* out = (float*)d_out;

    static bool attr_done = false;
    if (!attr_done) {
        cudaFuncSetAttribute(vq_gemm_kernel,
                             cudaFuncAttributeMaxDynamicSharedMemorySize, SM_GEMM);
        cudaFuncSetAttribute(gr_kernel,
                             cudaFuncAttributeMaxDynamicSharedMemorySize, SM_GR);
        attr_done = true;
    }

    prep_cb_kernel<<<1024, 256>>>(cb);              // #1
    prep_x_kernel<<<2048, 256>>>(x);                // #2
    {
        dim3 grid(256, 4);
        vq_gemm_kernel<<<grid, 512, SM_GEMM>>>();   // #3
    }
    gr_kernel<<<256, 256, SM_GR>>>(x, cb, out);     // #4 (profiled)
    finalize_kernel<<<1, 1>>>(out);                 // #5
}

// round 16
// speedup vs baseline: 1.5413x; 1.5413x over previous
#include <cuda_runtime.h>
#include <cuda_fp16.h>
#include <cstdint>

// Problem constants
#define B_    32
#define C_    256
#define HW_   1024
#define N_    32768          // B_*HW_
#define K_    1024
#define QSIZE 8388608        // B_*C_*HW_
#define CAPS  16             // candidates per (row, n-slice)
#define DELTA 2.5e-3f

__device__ float g_enorm[K_];
__device__ float g_apart[4 * N_];           // per-64c-block partial |z|^2
__device__ float g_loss;
__device__ int   g_idx[N_];
__device__ int   g_cnt[N_ * 4];             // per (row, slice) candidate count
__device__ int   g_cand[(size_t)N_ * 4 * CAPS];
__device__ __half g_Ah[(size_t)N_ * C_];    // x rows hi plane, [n][256]
__device__ __half g_Am[(size_t)N_ * C_];    // x rows residual plane
__device__ __half g_Bh[(size_t)K_ * C_];    // codebook hi plane, [k][256]

// ---------------------------------------------------------------------------
// PTX helpers
// ---------------------------------------------------------------------------
__device__ __forceinline__ uint32_t smem_u32(const void* p) {
    uint32_t a;
    asm("{ .reg .u64 t; cvta.to.shared.u64 t, %1; cvt.u32.u64 %0, t; }" : "=r"(a) : "l"(p));
    return a;
}
__device__ __forceinline__ void cp16(uint32_t daddr, const void* g) {
    asm volatile("cp.async.cg.shared.global [%0], [%1], 16;" :: "r"(daddr), "l"(g));
}
#define CP_COMMIT()  asm volatile("cp.async.commit_group;")
#define CP_WAIT0()   asm volatile("cp.async.wait_group 0;")

__device__ __forceinline__ void ldsm4(uint32_t* r, uint32_t addr) {
    asm volatile("ldmatrix.sync.aligned.m8n8.x4.shared.b16 {%0,%1,%2,%3}, [%4];"
        : "=r"(r[0]), "=r"(r[1]), "=r"(r[2]), "=r"(r[3]) : "r"(addr));
}
__device__ __forceinline__ void mma16816(float* d, const uint32_t* a, const uint32_t* b) {
    asm volatile(
        "mma.sync.aligned.m16n8k16.row.col.f32.f16.f16.f32 "
        "{%0,%1,%2,%3},{%4,%5,%6,%7},{%8,%9},{%0,%1,%2,%3};"
        : "+f"(d[0]), "+f"(d[1]), "+f"(d[2]), "+f"(d[3])
        : "r"(a[0]), "r"(a[1]), "r"(a[2]), "r"(a[3]), "r"(b[0]), "r"(b[1]));
}

// ---------------------------------------------------------------------------
// Launch #1: codebook -> fp16 plane; blocks 0-3 also enorm; thread 0 zeroes loss.
// ---------------------------------------------------------------------------
__global__ void prep_cb_kernel(const float* __restrict__ cb) {
    int i = blockIdx.x * blockDim.x + threadIdx.x;   // 0 .. 262143
    if (i == 0) g_loss = 0.0f;
    g_Bh[i] = __float2half_rn(cb[i]);
    if (blockIdx.x < 4) {
        int k = blockIdx.x * blockDim.x + threadIdx.x;
        const float4* row = reinterpret_cast<const float4*>(cb + (size_t)k * C_);
        float s = 0.f;
        #pragma unroll
        for (int q = 0; q < C_ / 4; ++q) {
            float4 v = row[q];
            s += v.x * v.x + v.y * v.y + v.z * v.z + v.w * v.w;
        }
        g_enorm[k] = s;
    }
}

// ---------------------------------------------------------------------------
// Launch #2: transpose x -> 2 fp16 planes + |z|^2 partials (one sync).
// ---------------------------------------------------------------------------
__global__ void prep_x_kernel(const float* __restrict__ x) {
    __shared__ float tile[64][65];
    __shared__ float sp[16][8];
    int bid = blockIdx.x;          // 2048 blocks
    int b   = bid >> 6;
    int rem = bid & 63;
    int cb4 = rem >> 4;
    int c0  = cb4 << 6;
    int hw0 = (rem & 15) << 6;
    int tid = threadIdx.x;
    int lane = tid & 31, wid = tid >> 5;

    #pragma unroll
    for (int i = 0; i < 16; ++i) {
        int cc = i * 4 + (tid >> 6);
        int hw = tid & 63;
        tile[cc][hw] = x[((size_t)b * C_ + c0 + cc) * HW_ + hw0 + hw];
    }
    __syncthreads();
    #pragma unroll
    for (int i = 0; i < 16; ++i) {
        int hh = i * 4 + (tid >> 6);
        int ci = tid & 63;
        float v = tile[ci][hh];
        __half h = __float2half_rn(v);
        __half m = __float2half_rn(v - __half2float(h));
        size_t o = (size_t)(b * HW_ + hw0 + hh) * C_ + c0 + ci;
        g_Ah[o] = h; g_Am[o] = m;

        float s = v * v;
        #pragma unroll
        for (int off = 16; off; off >>= 1) s += __shfl_xor_sync(0xffffffffu, s, off);
        if (lane == 0) sp[i][wid] = s;
    }
    __syncthreads();
    if (tid < 64) {
        int i = tid >> 2, pr = tid & 3;
        g_apart[cb4 * N_ + b * HW_ + hw0 + i * 4 + pr] = sp[i][2 * pr] + sp[i][2 * pr + 1];
    }
}

// ---------------------------------------------------------------------------
// Launch #3: GEMM (R14 measured-best, unchanged). grid (256,4), 512 threads.
// ---------------------------------------------------------------------------
#define APITCH 72
#define ABUF_B (128 * APITCH * 2)
#define BBUF_B (256 * APITCH * 2)
#define SDIST_OFF (2 * ABUF_B + 2 * BBUF_B)
#define DPITCH 258
#define SM_GEMM (SDIST_OFF + 128 * DPITCH * 2)
#define NKC 4

__global__ __launch_bounds__(512, 1)
void vq_gemm_kernel()
{
    extern __shared__ __align__(16) char dsm[];
    const uint32_t smA = smem_u32(dsm);
    const uint32_t smB = smA + 2 * ABUF_B;

    __shared__ float sEn[256];

    const int tid  = threadIdx.x;
    const int lane = tid & 31;
    const int wid  = tid >> 5;
    const int wm   = wid >> 3;
    const int wn   = wid & 7;

    const int m0 = blockIdx.x << 7;
    const int n0 = blockIdx.y << 8;

    if (tid < 256) sEn[tid] = g_enorm[n0 + tid];

    const __half* Ag = g_Ah + (size_t)m0 * C_;
    const __half* Bg = g_Bh + (size_t)n0 * C_;

    float acc[4][4][4];
    #pragma unroll
    for (int mf = 0; mf < 4; ++mf)
        #pragma unroll
        for (int nf = 0; nf < 4; ++nf)
            #pragma unroll
            for (int q = 0; q < 4; ++q) acc[mf][nf][q] = 0.f;

    const uint32_t aAddr0 = smA + (uint32_t)(((wm * 64 + (lane & 15)) * APITCH + ((lane >> 4) << 3)) * 2);
    const uint32_t bAddr0 = smB + (uint32_t)(((wn * 32 + (lane & 7) + ((lane >> 4) << 3)) * APITCH
                                              + (((lane >> 3) & 1) << 3)) * 2);

    {
        #pragma unroll
        for (int j = 0; j < 2; ++j) {
            int p = tid + j * 512, row = p >> 3, kp = (p & 7) << 3;
            cp16(smA + (uint32_t)((row * APITCH + kp) * 2), Ag + (size_t)row * C_ + kp);
        }
        #pragma unroll
        for (int j = 0; j < 4; ++j) {
            int p = tid + j * 512, row = p >> 3, kp = (p & 7) << 3;
            cp16(smB + (uint32_t)((row * APITCH + kp) * 2), Bg + (size_t)row * C_ + kp);
        }
        CP_COMMIT();
    }

    for (int it = 0; it < NKC; ++it) {
        CP_WAIT0();
        __syncthreads();

        if (it + 1 < NKC) {
            const int nb = (it + 1) & 1;
            const int k0 = (it + 1) << 6;
            #pragma unroll
            for (int j = 0; j < 2; ++j) {
                int p = tid + j * 512, row = p >> 3, kp = (p & 7) << 3;
                cp16(smA + (uint32_t)(nb * ABUF_B + (row * APITCH + kp) * 2),
                     Ag + (size_t)row * C_ + k0 + kp);
            }
            #pragma unroll
            for (int j = 0; j < 4; ++j) {
                int p = tid + j * 512, row = p >> 3, kp = (p & 7) << 3;
                cp16(smB + (uint32_t)(nb * BBUF_B + (row * APITCH + kp) * 2),
                     Bg + (size_t)row * C_ + k0 + kp);
            }
            CP_COMMIT();
        }

        const int buf = it & 1;
        const uint32_t aB = aAddr0 + (uint32_t)(buf * ABUF_B);
        const uint32_t bB = bAddr0 + (uint32_t)(buf * BBUF_B);

        #pragma unroll
        for (int ks = 0; ks < 4; ++ks) {
            uint32_t a[4][4], bfr[2][4];
            #pragma unroll
            for (int mf = 0; mf < 4; ++mf)
                ldsm4(a[mf], aB + (uint32_t)(mf * 16 * APITCH * 2 + ks * 32));
            #pragma unroll
            for (int nb2 = 0; nb2 < 2; ++nb2)
                ldsm4(bfr[nb2], bB + (uint32_t)(nb2 * 16 * APITCH * 2 + ks * 32));
            #pragma unroll
            for (int mf = 0; mf < 4; ++mf)
                #pragma unroll
                for (int nf = 0; nf < 4; ++nf)
                    mma16816(acc[mf][nf], a[mf], &bfr[nf >> 1][(nf & 1) << 1]);
        }
    }

    const int rb  = (wm << 6) + (lane >> 2);
    const int cl0 = (wn << 5) + ((lane & 3) << 1);
    #pragma unroll
    for (int mf = 0; mf < 4; ++mf) {
        #pragma unroll
        for (int hv = 0; hv < 2; ++hv) {
            int lrow = rb + mf * 16 + hv * 8;
            #pragma unroll
            for (int nf = 0; nf < 4; ++nf) {
                int cl = cl0 + nf * 8;
                float t0 = fmaf(-2.0f, acc[mf][nf][hv * 2 + 0], sEn[cl]);
                float t1 = fmaf(-2.0f, acc[mf][nf][hv * 2 + 1], sEn[cl + 1]);
                *reinterpret_cast<__half2*>(dsm + SDIST_OFF + ((size_t)lrow * DPITCH + cl) * 2)
                    = __floats2half2_rn(t0, t1);
            }
        }
    }
    __syncthreads();

    if (tid < 128) {
        const __half2* rowp =
            reinterpret_cast<const __half2*>(dsm + SDIST_OFF + (size_t)tid * DPITCH * 2);
        float mn = 3.4e38f;
        #pragma unroll 8
        for (int i = 0; i < 128; ++i) {
            __half2 h2 = rowp[i];
            float f0 = __low2float(h2), f1 = __high2float(h2);
            if (f0 < mn) mn = f0;
            if (f1 < mn) mn = f1;
        }
        float thr = mn + DELTA;
        int slot = ((m0 + tid) << 2) + blockIdx.y;
        int* cl = g_cand + (size_t)slot * CAPS;
        int cnt = 0;
        #pragma unroll 8
        for (int i = 0; i < 128; ++i) {
            __half2 h2 = rowp[i];
            float f0 = __low2float(h2), f1 = __high2float(h2);
            if (f0 <= thr && cnt < CAPS) cl[cnt++] = n0 + 2 * i;
            if (f1 <= thr && cnt < CAPS) cl[cnt++] = n0 + 2 * i + 1;
        }
        g_cnt[slot] = cnt;
    }
}

// ---------------------------------------------------------------------------
// Launch #4 (PROFILED): recheck (R14-proven). 1 warp per row, warp-collective
// exact fp32 dot per candidate; packed (value,index) min = lowest index ties.
// ---------------------------------------------------------------------------
__global__ __launch_bounds__(256)
void recheck_kernel(const float* __restrict__ cb)
{
    __shared__ int cands[8][4 * CAPS];
    const int lane = threadIdx.x & 31;
    const int wid  = threadIdx.x >> 5;
    const int row  = blockIdx.x * 8 + wid;

    float xr[8];
    {
        const __half* ah = g_Ah + (size_t)row * C_;
        const __half* am = g_Am + (size_t)row * C_;
        uint4 hvv = *reinterpret_cast<const uint4*>(ah + lane * 8);
        uint4 mvv = *reinterpret_cast<const uint4*>(am + lane * 8);
        const __half* hp = reinterpret_cast<const __half*>(&hvv);
        const __half* mp = reinterpret_cast<const __half*>(&mvv);
        #pragma unroll
        for (int j = 0; j < 8; ++j)
            xr[j] = __half2float(hp[j]) + __half2float(mp[j]);
    }

    int nct = 0;
    #pragma unroll
    for (int y = 0; y < 4; ++y) {
        int slot = row * 4 + y;
        int cy = g_cnt[slot];
        if (lane < cy) cands[wid][nct + lane] = g_cand[(size_t)slot * CAPS + lane];
        nct += cy;
    }
    __syncwarp();

    float a = ((g_apart[row] + g_apart[N_ + row]) + g_apart[2 * N_ + row]) + g_apart[3 * N_ + row];
    unsigned long long eb = 0xFFFFFFFFFFFFFFFFull;
    for (int j = 0; j < nct; ++j) {
        int k = cands[wid][j];
        const float4* cr = reinterpret_cast<const float4*>(cb + (size_t)k * C_) + lane * 2;
        float4 c0 = cr[0], c1 = cr[1];
        float p = 0.f;
        p = fmaf(xr[0], c0.x, p); p = fmaf(xr[1], c0.y, p);
        p = fmaf(xr[2], c0.z, p); p = fmaf(xr[3], c0.w, p);
        p = fmaf(xr[4], c1.x, p); p = fmaf(xr[5], c1.y, p);
        p = fmaf(xr[6], c1.z, p); p = fmaf(xr[7], c1.w, p);
        #pragma unroll
        for (int off = 16; off; off >>= 1)
            p += __shfl_xor_sync(0xffffffffu, p, off);
        float s = (a + g_enorm[k]) - 2.0f * p;
        unsigned long long pk =
            ((unsigned long long)__float_as_uint(s) << 32) | (unsigned)k;
        if (pk < eb) eb = pk;
    }
    if (lane == 0) g_idx[row] = (int)(unsigned)(eb & 0xFFFFFFFFull);
}

// ---------------------------------------------------------------------------
// Launch #5: gather, c-sliced for occupancy. grid 1024 = 256 row-groups x 4
// c-slices; each block stages 128 rows x 64 c of the codebook (coalesced)
// into 33 KB smem, then the proven x/out main loop.
// ---------------------------------------------------------------------------
#define GP2 65
#define SM_GATHER (128 * GP2 * 4)   // 33280

__global__ __launch_bounds__(256)
void gather_kernel(const float* __restrict__ x,
                   const float* __restrict__ cb,
                   float* __restrict__ out)
{
    extern __shared__ __align__(16) float sq[];   // [128][GP2]
    __shared__ int   srow[128];
    __shared__ float wsum[8];

    const int tid  = threadIdx.x;
    const int lane = tid & 31;
    const int w    = tid >> 5;
    const int g    = blockIdx.x >> 2;   // row group 0..255
    const int cs   = blockIdx.x & 3;    // c-slice 0..3
    const int c0   = cs << 6;
    const int b    = g >> 3;
    const int hw0  = (g & 7) << 7;
    const int m0   = g << 7;

    if (tid < 128) {
        int idx = g_idx[m0 + tid];
        srow[tid] = idx;
        if (cs == 0) out[QSIZE + 1 + m0 + tid] = (float)idx;
    }
    __syncthreads();

    // stage: 128 rows x 64 c, coalesced 256B per row-slice
    #pragma unroll
    for (int r = 0; r < 16; ++r) {
        int m = w * 16 + r;
        const float2 v = *reinterpret_cast<const float2*>(
            cb + (size_t)srow[m] * C_ + c0 + 2 * lane);
        sq[m * GP2 + 2 * lane]     = v.x;
        sq[m * GP2 + 2 * lane + 1] = v.y;
    }
    __syncthreads();

    const float* xblk = x   + (size_t)b * (C_ * HW_) + hw0;
    float*       qblk = out + (size_t)b * (C_ * HW_) + hw0;
    float lsum = 0.f;
    #pragma unroll
    for (int it = 0; it < 8; ++it) {
        int l   = it * 256 + tid;           // 0..2047
        int m4  = (l & 31) << 2;
        int cl  = l >> 5;                   // 0..63
        int c   = c0 + cl;
        float4 xv = *reinterpret_cast<const float4*>(xblk + c * HW_ + m4);
        float q0 = sq[(m4 + 0) * GP2 + cl];
        float q1 = sq[(m4 + 1) * GP2 + cl];
        float q2 = sq[(m4 + 2) * GP2 + cl];
        float q3 = sq[(m4 + 3) * GP2 + cl];
        float d0 = q0 - xv.x, d1 = q1 - xv.y, d2 = q2 - xv.z, d3 = q3 - xv.w;
        float4 o;
        o.x = xv.x + d0; o.y = xv.y + d1; o.z = xv.z + d2; o.w = xv.w + d3;
        *reinterpret_cast<float4*>(qblk + c * HW_ + m4) = o;
        lsum += d0 * d0 + d1 * d1 + d2 * d2 + d3 * d3;
    }

    #pragma unroll
    for (int off = 16; off; off >>= 1)
        lsum += __shfl_xor_sync(0xffffffffu, lsum, off);
    if (lane == 0) wsum[w] = lsum;
    __syncthreads();
    if (tid == 0) {
        float s = 0.f;
        #pragma unroll
        for (int w2 = 0; w2 < 8; ++w2) s += wsum[w2];
        atomicAdd(&g_loss, s);
    }
}

__global__ void finalize_kernel(float* __restrict__ out) {
    out[QSIZE] = 1.25f * g_loss * (1.0f / (float)QSIZE);
}

extern "C" void kernel_launch(void* const* d_in, const int* in_sizes, int n_in,
                              void* d_out, int out_size) {
    (void)in_sizes; (void)n_in; (void)out_size;
    const float* x  = (const float*)d_in[0];
    const float* cb = (const float*)d_in[1];
    float* out = (float*)d_out;

    static bool attr_done = false;
    if (!attr_done) {
        cudaFuncSetAttribute(vq_gemm_kernel,
                             cudaFuncAttributeMaxDynamicSharedMemorySize, SM_GEMM);
        cudaFuncSetAttribute(gather_kernel,
                             cudaFuncAttributeMaxDynamicSharedMemorySize, SM_GATHER);
        attr_done = true;
    }

    prep_cb_kernel<<<1024, 256>>>(cb);                  // #1
    prep_x_kernel<<<2048, 256>>>(x);                    // #2
    {
        dim3 grid(256, 4);
        vq_gemm_kernel<<<grid, 512, SM_GEMM>>>();       // #3
    }
    recheck_kernel<<<4096, 256>>>(cb);                  // #4 (profiled)
    gather_kernel<<<1024, 256, SM_GATHER>>>(x, cb, out); // #5
    finalize_kernel<<<1, 1>>>(out);                     // #6
}

// round 17
// speedup vs baseline: 1.8404x; 1.1940x over previous
#include <cuda_runtime.h>
#include <cuda_fp16.h>
#include <cstdint>

// Problem constants
#define B_    32
#define C_    256
#define HW_   1024
#define N_    32768          // B_*HW_
#define K_    1024
#define QSIZE 8388608        // B_*C_*HW_
#define CAPS  16             // candidates per (row, n-slice)
#define DELTA  2.5e-3f       // slice-local screen window
#define MARGIN 2e-3f         // global-min recheck filter (>= 2*eps bound)

__device__ float g_enorm[K_];
__device__ float g_apart[4 * N_];           // per-64c-block partial |z|^2
__device__ float g_loss;
__device__ int   g_idx[N_];
__device__ int   g_cnt[N_ * 4];             // per (row, slice) candidate count
__device__ float g_smin[N_ * 4];            // per (row, slice) screen min
__device__ unsigned int g_cand[(size_t)N_ * 4 * CAPS];  // (half bits << 16) | k
__device__ __half g_Ah[(size_t)N_ * C_];    // x rows hi plane, [n][256]
__device__ __half g_Am[(size_t)N_ * C_];    // x rows residual plane
__device__ __half g_Bh[(size_t)K_ * C_];    // codebook hi plane, [k][256]

// ---------------------------------------------------------------------------
// PTX helpers
// ---------------------------------------------------------------------------
__device__ __forceinline__ uint32_t smem_u32(const void* p) {
    uint32_t a;
    asm("{ .reg .u64 t; cvta.to.shared.u64 t, %1; cvt.u32.u64 %0, t; }" : "=r"(a) : "l"(p));
    return a;
}
__device__ __forceinline__ void cp16(uint32_t daddr, const void* g) {
    asm volatile("cp.async.cg.shared.global [%0], [%1], 16;" :: "r"(daddr), "l"(g));
}
#define CP_COMMIT()  asm volatile("cp.async.commit_group;")
#define CP_WAIT0()   asm volatile("cp.async.wait_group 0;")

__device__ __forceinline__ void ldsm4(uint32_t* r, uint32_t addr) {
    asm volatile("ldmatrix.sync.aligned.m8n8.x4.shared.b16 {%0,%1,%2,%3}, [%4];"
        : "=r"(r[0]), "=r"(r[1]), "=r"(r[2]), "=r"(r[3]) : "r"(addr));
}
__device__ __forceinline__ void mma16816(float* d, const uint32_t* a, const uint32_t* b) {
    asm volatile(
        "mma.sync.aligned.m16n8k16.row.col.f32.f16.f16.f32 "
        "{%0,%1,%2,%3},{%4,%5,%6,%7},{%8,%9},{%0,%1,%2,%3};"
        : "+f"(d[0]), "+f"(d[1]), "+f"(d[2]), "+f"(d[3])
        : "r"(a[0]), "r"(a[1]), "r"(a[2]), "r"(a[3]), "r"(b[0]), "r"(b[1]));
}

// ---------------------------------------------------------------------------
// Launch #1: fused prep. Blocks [0,2048): transpose x -> fp16 planes + |z|^2
// partials. Blocks [2048,3072): codebook -> fp16 plane (+ enorm, + zero loss).
// ---------------------------------------------------------------------------
__global__ void prep_kernel(const float* __restrict__ x,
                            const float* __restrict__ cb) {
    __shared__ float tile[64][65];
    __shared__ float sp[16][8];
    int tid = threadIdx.x;

    if (blockIdx.x >= 2048) {
        int cbid = blockIdx.x - 2048;
        int i = cbid * 256 + tid;              // 0 .. 262143
        if (i == 0) g_loss = 0.0f;
        g_Bh[i] = __float2half_rn(cb[i]);
        if (cbid < 4) {
            int k = cbid * 256 + tid;
            const float4* row = reinterpret_cast<const float4*>(cb + (size_t)k * C_);
            float s = 0.f;
            #pragma unroll
            for (int q = 0; q < C_ / 4; ++q) {
                float4 v = row[q];
                s += v.x * v.x + v.y * v.y + v.z * v.z + v.w * v.w;
            }
            g_enorm[k] = s;
        }
        return;
    }

    int bid = blockIdx.x;          // 0..2047
    int b   = bid >> 6;
    int rem = bid & 63;
    int cb4 = rem >> 4;
    int c0  = cb4 << 6;
    int hw0 = (rem & 15) << 6;
    int lane = tid & 31, wid = tid >> 5;

    #pragma unroll
    for (int i = 0; i < 16; ++i) {
        int cc = i * 4 + (tid >> 6);
        int hw = tid & 63;
        tile[cc][hw] = x[((size_t)b * C_ + c0 + cc) * HW_ + hw0 + hw];
    }
    __syncthreads();
    #pragma unroll
    for (int i = 0; i < 16; ++i) {
        int hh = i * 4 + (tid >> 6);
        int ci = tid & 63;
        float v = tile[ci][hh];
        __half h = __float2half_rn(v);
        __half m = __float2half_rn(v - __half2float(h));
        size_t o = (size_t)(b * HW_ + hw0 + hh) * C_ + c0 + ci;
        g_Ah[o] = h; g_Am[o] = m;

        float s = v * v;
        #pragma unroll
        for (int off = 16; off; off >>= 1) s += __shfl_xor_sync(0xffffffffu, s, off);
        if (lane == 0) sp[i][wid] = s;
    }
    __syncthreads();
    if (tid < 64) {
        int i = tid >> 2, pr = tid & 3;
        g_apart[cb4 * N_ + b * HW_ + hw0 + i * 4 + pr] = sp[i][2 * pr] + sp[i][2 * pr + 1];
    }
}

// ---------------------------------------------------------------------------
// Launch #2: GEMM (R14 mainloop, frozen). grid (256,4), 512 threads.
// New epilogue: parallel 4-threads-per-row scan (bank-rotated), slice min to
// g_smin, candidates packed with fp16 screen bits, smem-atomic append.
// ---------------------------------------------------------------------------
#define APITCH 72
#define ABUF_B (128 * APITCH * 2)
#define BBUF_B (256 * APITCH * 2)
#define SDIST_OFF (2 * ABUF_B + 2 * BBUF_B)
#define DPITCH 258
#define SM_GEMM (SDIST_OFF + 128 * DPITCH * 2)
#define NKC 4

__global__ __launch_bounds__(512, 1)
void vq_gemm_kernel()
{
    extern __shared__ __align__(16) char dsm[];
    const uint32_t smA = smem_u32(dsm);
    const uint32_t smB = smA + 2 * ABUF_B;

    __shared__ float sEn[256];
    __shared__ int   sCnt[128];

    const int tid  = threadIdx.x;
    const int lane = tid & 31;
    const int wid  = tid >> 5;
    const int wm   = wid >> 3;
    const int wn   = wid & 7;

    const int m0 = blockIdx.x << 7;
    const int n0 = blockIdx.y << 8;

    if (tid < 256) sEn[tid] = g_enorm[n0 + tid];
    if (tid < 128) sCnt[tid] = 0;

    const __half* Ag = g_Ah + (size_t)m0 * C_;
    const __half* Bg = g_Bh + (size_t)n0 * C_;

    float acc[4][4][4];
    #pragma unroll
    for (int mf = 0; mf < 4; ++mf)
        #pragma unroll
        for (int nf = 0; nf < 4; ++nf)
            #pragma unroll
            for (int q = 0; q < 4; ++q) acc[mf][nf][q] = 0.f;

    const uint32_t aAddr0 = smA + (uint32_t)(((wm * 64 + (lane & 15)) * APITCH + ((lane >> 4) << 3)) * 2);
    const uint32_t bAddr0 = smB + (uint32_t)(((wn * 32 + (lane & 7) + ((lane >> 4) << 3)) * APITCH
                                              + (((lane >> 3) & 1) << 3)) * 2);

    {
        #pragma unroll
        for (int j = 0; j < 2; ++j) {
            int p = tid + j * 512, row = p >> 3, kp = (p & 7) << 3;
            cp16(smA + (uint32_t)((row * APITCH + kp) * 2), Ag + (size_t)row * C_ + kp);
        }
        #pragma unroll
        for (int j = 0; j < 4; ++j) {
            int p = tid + j * 512, row = p >> 3, kp = (p & 7) << 3;
            cp16(smB + (uint32_t)((row * APITCH + kp) * 2), Bg + (size_t)row * C_ + kp);
        }
        CP_COMMIT();
    }

    for (int it = 0; it < NKC; ++it) {
        CP_WAIT0();
        __syncthreads();

        if (it + 1 < NKC) {
            const int nb = (it + 1) & 1;
            const int k0 = (it + 1) << 6;
            #pragma unroll
            for (int j = 0; j < 2; ++j) {
                int p = tid + j * 512, row = p >> 3, kp = (p & 7) << 3;
                cp16(smA + (uint32_t)(nb * ABUF_B + (row * APITCH + kp) * 2),
                     Ag + (size_t)row * C_ + k0 + kp);
            }
            #pragma unroll
            for (int j = 0; j < 4; ++j) {
                int p = tid + j * 512, row = p >> 3, kp = (p & 7) << 3;
                cp16(smB + (uint32_t)(nb * BBUF_B + (row * APITCH + kp) * 2),
                     Bg + (size_t)row * C_ + k0 + kp);
            }
            CP_COMMIT();
        }

        const int buf = it & 1;
        const uint32_t aB = aAddr0 + (uint32_t)(buf * ABUF_B);
        const uint32_t bB = bAddr0 + (uint32_t)(buf * BBUF_B);

        #pragma unroll
        for (int ks = 0; ks < 4; ++ks) {
            uint32_t a[4][4], bfr[2][4];
            #pragma unroll
            for (int mf = 0; mf < 4; ++mf)
                ldsm4(a[mf], aB + (uint32_t)(mf * 16 * APITCH * 2 + ks * 32));
            #pragma unroll
            for (int nb2 = 0; nb2 < 2; ++nb2)
                ldsm4(bfr[nb2], bB + (uint32_t)(nb2 * 16 * APITCH * 2 + ks * 32));
            #pragma unroll
            for (int mf = 0; mf < 4; ++mf)
                #pragma unroll
                for (int nf = 0; nf < 4; ++nf)
                    mma16816(acc[mf][nf], a[mf], &bfr[nf >> 1][(nf & 1) << 1]);
        }
    }

    // ---- dist = e - 2m -> fp16 smem (acc dies here) -------------------------
    const int rb  = (wm << 6) + (lane >> 2);
    const int cl0 = (wn << 5) + ((lane & 3) << 1);
    #pragma unroll
    for (int mf = 0; mf < 4; ++mf) {
        #pragma unroll
        for (int hv = 0; hv < 2; ++hv) {
            int lrow = rb + mf * 16 + hv * 8;
            #pragma unroll
            for (int nf = 0; nf < 4; ++nf) {
                int cl = cl0 + nf * 8;
                float t0 = fmaf(-2.0f, acc[mf][nf][hv * 2 + 0], sEn[cl]);
                float t1 = fmaf(-2.0f, acc[mf][nf][hv * 2 + 1], sEn[cl + 1]);
                *reinterpret_cast<__half2*>(dsm + SDIST_OFF + ((size_t)lrow * DPITCH + cl) * 2)
                    = __floats2half2_rn(t0, t1);
            }
        }
    }
    __syncthreads();

    // ---- parallel scan: 4 threads per row, bank-rotated indices ------------
    {
        const int row = tid >> 2;
        const int q   = tid & 3;
        const uint32_t rbase = (uint32_t)(SDIST_OFF + row * (DPITCH * 2));
        float mn = 3.4e38f;
        #pragma unroll 8
        for (int ii = 0; ii < 32; ++ii) {
            int j = q * 32 + ((ii + 8 * q) & 31);
            __half2 h2 = *reinterpret_cast<const __half2*>(dsm + rbase + j * 4);
            float f0 = __low2float(h2), f1 = __high2float(h2);
            if (f0 < mn) mn = f0;
            if (f1 < mn) mn = f1;
        }
        mn = fminf(mn, __shfl_xor_sync(0xffffffffu, mn, 1));
        mn = fminf(mn, __shfl_xor_sync(0xffffffffu, mn, 2));
        const int slot = ((m0 + row) << 2) + blockIdx.y;
        if (q == 0) g_smin[slot] = mn;
        const float thr = mn + DELTA;
        unsigned int* cl = g_cand + (size_t)slot * CAPS;
        #pragma unroll 8
        for (int ii = 0; ii < 32; ++ii) {
            int j = q * 32 + ((ii + 8 * q) & 31);
            __half2 h2 = *reinterpret_cast<const __half2*>(dsm + rbase + j * 4);
            float f0 = __low2float(h2), f1 = __high2float(h2);
            if (f0 <= thr) {
                int pos = atomicAdd(&sCnt[row], 1);
                if (pos < CAPS)
                    cl[pos] = ((unsigned)__half_as_ushort(__low2half(h2)) << 16)
                            | (unsigned)(n0 + 2 * j);
            }
            if (f1 <= thr) {
                int pos = atomicAdd(&sCnt[row], 1);
                if (pos < CAPS)
                    cl[pos] = ((unsigned)__half_as_ushort(__high2half(h2)) << 16)
                            | (unsigned)(n0 + 2 * j + 1);
            }
        }
    }
    __syncthreads();
    if (tid < 128) {
        int c = sCnt[tid]; if (c > CAPS) c = CAPS;
        g_cnt[((m0 + tid) << 2) + blockIdx.y] = c;
    }
}

// ---------------------------------------------------------------------------
// Launch #3: recheck. 1 warp per row. Global-min filter (warp-uniform) then
// warp-collective exact fp32 dot; packed (value,index) min; writes indices.
// ---------------------------------------------------------------------------
__global__ __launch_bounds__(256)
void recheck_kernel(const float* __restrict__ cb, float* __restrict__ out)
{
    __shared__ unsigned int cands[8][4 * CAPS];
    const int lane = threadIdx.x & 31;
    const int wid  = threadIdx.x >> 5;
    const int row  = blockIdx.x * 8 + wid;

    float xr[8];
    {
        const __half* ah = g_Ah + (size_t)row * C_;
        const __half* am = g_Am + (size_t)row * C_;
        uint4 hvv = *reinterpret_cast<const uint4*>(ah + lane * 8);
        uint4 mvv = *reinterpret_cast<const uint4*>(am + lane * 8);
        const __half* hp = reinterpret_cast<const __half*>(&hvv);
        const __half* mp = reinterpret_cast<const __half*>(&mvv);
        #pragma unroll
        for (int j = 0; j < 8; ++j)
            xr[j] = __half2float(hp[j]) + __half2float(mp[j]);
    }

    int nct = 0;
    #pragma unroll
    for (int y = 0; y < 4; ++y) {
        int slot = row * 4 + y;
        int cy = g_cnt[slot];
        if (lane < cy) cands[wid][nct + lane] = g_cand[(size_t)slot * CAPS + lane];
        nct += cy;
    }
    const float gmin = fminf(fminf(g_smin[row * 4 + 0], g_smin[row * 4 + 1]),
                             fminf(g_smin[row * 4 + 2], g_smin[row * 4 + 3]));
    const float thrG = gmin + MARGIN;
    __syncwarp();

    float a = ((g_apart[row] + g_apart[N_ + row]) + g_apart[2 * N_ + row]) + g_apart[3 * N_ + row];
    unsigned long long eb = 0xFFFFFFFFFFFFFFFFull;
    for (int j = 0; j < nct; ++j) {
        unsigned e = cands[wid][j];
        float sv = __half2float(__ushort_as_half((unsigned short)(e >> 16)));
        if (sv > thrG) continue;              // warp-uniform branch
        int k = (int)(e & 0xFFFFu);
        const float4* cr = reinterpret_cast<const float4*>(cb + (size_t)k * C_) + lane * 2;
        float4 c0 = cr[0], c1 = cr[1];
        float p = 0.f;
        p = fmaf(xr[0], c0.x, p); p = fmaf(xr[1], c0.y, p);
        p = fmaf(xr[2], c0.z, p); p = fmaf(xr[3], c0.w, p);
        p = fmaf(xr[4], c1.x, p); p = fmaf(xr[5], c1.y, p);
        p = fmaf(xr[6], c1.z, p); p = fmaf(xr[7], c1.w, p);
        #pragma unroll
        for (int off = 16; off; off >>= 1)
            p += __shfl_xor_sync(0xffffffffu, p, off);
        float s = (a + g_enorm[k]) - 2.0f * p;
        unsigned long long pk =
            ((unsigned long long)__float_as_uint(s) << 32) | (unsigned)k;
        if (pk < eb) eb = pk;
    }
    if (lane == 0) {
        int idx = (int)(unsigned)(eb & 0xFFFFFFFFull);
        g_idx[row] = idx;
        out[QSIZE + 1 + row] = (float)idx;
    }
}

// ---------------------------------------------------------------------------
// Launch #4 (PROFILED): gather, c-sliced for occupancy (R16-proven).
// ---------------------------------------------------------------------------
#define GP2 65
#define SM_GATHER (128 * GP2 * 4)   // 33280

__global__ __launch_bounds__(256)
void gather_kernel(const float* __restrict__ x,
                   const float* __restrict__ cb,
                   float* __restrict__ out)
{
    extern __shared__ __align__(16) float sq[];   // [128][GP2]
    __shared__ int   srow[128];
    __shared__ float wsum[8];

    const int tid  = threadIdx.x;
    const int lane = tid & 31;
    const int w    = tid >> 5;
    const int g    = blockIdx.x >> 2;   // row group 0..255
    const int cs   = blockIdx.x & 3;    // c-slice 0..3
    const int c0   = cs << 6;
    const int b    = g >> 3;
    const int hw0  = (g & 7) << 7;
    const int m0   = g << 7;

    if (tid < 128) srow[tid] = g_idx[m0 + tid];
    __syncthreads();

    #pragma unroll
    for (int r = 0; r < 16; ++r) {
        int m = w * 16 + r;
        const float2 v = *reinterpret_cast<const float2*>(
            cb + (size_t)srow[m] * C_ + c0 + 2 * lane);
        sq[m * GP2 + 2 * lane]     = v.x;
        sq[m * GP2 + 2 * lane + 1] = v.y;
    }
    __syncthreads();

    const float* xblk = x   + (size_t)b * (C_ * HW_) + hw0;
    float*       qblk = out + (size_t)b * (C_ * HW_) + hw0;
    float lsum = 0.f;
    #pragma unroll
    for (int it = 0; it < 8; ++it) {
        int l   = it * 256 + tid;
        int m4  = (l & 31) << 2;
        int cl  = l >> 5;
        int c   = c0 + cl;
        float4 xv = *reinterpret_cast<const float4*>(xblk + c * HW_ + m4);
        float q0 = sq[(m4 + 0) * GP2 + cl];
        float q1 = sq[(m4 + 1) * GP2 + cl];
        float q2 = sq[(m4 + 2) * GP2 + cl];
        float q3 = sq[(m4 + 3) * GP2 + cl];
        float d0 = q0 - xv.x, d1 = q1 - xv.y, d2 = q2 - xv.z, d3 = q3 - xv.w;
        float4 o;
        o.x = xv.x + d0; o.y = xv.y + d1; o.z = xv.z + d2; o.w = xv.w + d3;
        *reinterpret_cast<float4*>(qblk + c * HW_ + m4) = o;
        lsum += d0 * d0 + d1 * d1 + d2 * d2 + d3 * d3;
    }

    #pragma unroll
    for (int off = 16; off; off >>= 1)
        lsum += __shfl_xor_sync(0xffffffffu, lsum, off);
    if (lane == 0) wsum[w] = lsum;
    __syncthreads();
    if (tid == 0) {
        float s = 0.f;
        #pragma unroll
        for (int w2 = 0; w2 < 8; ++w2) s += wsum[w2];
        atomicAdd(&g_loss, s);
    }
}

__global__ void finalize_kernel(float* __restrict__ out) {
    out[QSIZE] = 1.25f * g_loss * (1.0f / (float)QSIZE);
}

extern "C" void kernel_launch(void* const* d_in, const int* in_sizes, int n_in,
                              void* d_out, int out_size) {
    (void)in_sizes; (void)n_in; (void)out_size;
    const float* x  = (const float*)d_in[0];
    const float* cb = (const float*)d_in[1];
    float* out = (float*)d_out;

    static bool attr_done = false;
    if (!attr_done) {
        cudaFuncSetAttribute(vq_gemm_kernel,
                             cudaFuncAttributeMaxDynamicSharedMemorySize, SM_GEMM);
        cudaFuncSetAttribute(gather_kernel,
                             cudaFuncAttributeMaxDynamicSharedMemorySize, SM_GATHER);
        attr_done = true;
    }

    prep_kernel<<<3072, 256>>>(x, cb);                   // #1
    {
        dim3 grid(256, 4);
        vq_gemm_kernel<<<grid, 512, SM_GEMM>>>();        // #2
    }
    recheck_kernel<<<4096, 256>>>(cb, out);              // #3
    gather_kernel<<<1024, 256, SM_GATHER>>>(x, cb, out); // #4 (profiled)
    finalize_kernel<<<1, 1>>>(out);                      // #5
}